// round 11
// baseline (speedup 1.0000x reference)
#include <cuda_runtime.h>
#include <cuda_fp16.h>
#include <cstdint>

#define IN_DIM    256
#define OUT_DIM   128
#define MAX_NODES 100000
#define MAX_EDGES 3200000

// ---------------- device scratch (static, no allocation) -------------------
__device__ __half g_hh[MAX_NODES * OUT_DIM];      // h = X @ W in fp16
__device__ float  g_wt[OUT_DIM * IN_DIM];         // W transposed: [128][256]
__device__ int    g_deg[MAX_NODES];
__device__ int    g_rowptr[MAX_NODES + 1];
__device__ int    g_fill[MAX_NODES];
__device__ int    g_bsum[128];
__device__ int2   g_esorted[MAX_EDGES];           // (src, val_bits) sorted by dst
__device__ int    g_dsorted[MAX_EDGES];           // dst per sorted edge

// ---------------------------------------------------------------------------
// W transpose: WT[n][k] = W[k][n]
// ---------------------------------------------------------------------------
__global__ void transpose_w_kernel(const float* __restrict__ W, float* __restrict__ WT)
{
    int i = blockIdx.x * blockDim.x + threadIdx.x;
    if (i < IN_DIM * OUT_DIM) {
        int k = i / OUT_DIM, n = i % OUT_DIM;
        WT[n * IN_DIM + k] = W[i];
    }
}

// ---------------------------------------------------------------------------
// GEMM via mma.sync tf32 (round-6 version: best measured, 57.7us).
// BM=128, BN=128, BK=32; 8 warps (4m x 2n); warp tile 32x64 (2x8 m16n8k8).
// Output stored fp16.
// ---------------------------------------------------------------------------
#define LDS_STRIDE 36   // 32 + 4 pad: frag LDS conflict-free, 16B-aligned rows

__device__ __forceinline__ uint32_t f2tf32(float f) {
    uint32_t r;
    asm("cvt.rna.tf32.f32 %0, %1;" : "=r"(r) : "f"(f));
    return r;
}

__global__ __launch_bounds__(256) void gemm_mma_kernel(
    const float* __restrict__ X, const float* __restrict__ WT,
    __half* __restrict__ Hh, int N)
{
    __shared__ uint32_t As[128 * LDS_STRIDE];   // [m][k] tf32 bits
    __shared__ uint32_t Bs[128 * LDS_STRIDE];   // [n][k] tf32 bits

    const int tid  = threadIdx.x;
    const int wid  = tid >> 5;
    const int lane = tid & 31;
    const int mw   = wid >> 1;        // 0..3
    const int nw   = wid & 1;         // 0..1
    const int rowBase = blockIdx.x * 128;

    const int qr = lane >> 2;         // 0..7
    const int qc = lane & 3;          // 0..3

    float acc[2][8][4];
#pragma unroll
    for (int mt = 0; mt < 2; mt++)
#pragma unroll
        for (int nt = 0; nt < 8; nt++)
#pragma unroll
            for (int j = 0; j < 4; j++) acc[mt][nt][j] = 0.0f;

    for (int k0 = 0; k0 < IN_DIM; k0 += 32) {
#pragma unroll
        for (int l = 0; l < 4; l++) {
            int idx = tid + l * 256;            // 0..1023
            int row = idx >> 3;
            int c4  = (idx & 7) * 4;
            float4 v;
            int grow = rowBase + row;
            if (grow < N)
                v = *reinterpret_cast<const float4*>(X + (size_t)grow * IN_DIM + k0 + c4);
            else
                v = make_float4(0.f, 0.f, 0.f, 0.f);
            uint4 t = make_uint4(f2tf32(v.x), f2tf32(v.y), f2tf32(v.z), f2tf32(v.w));
            *reinterpret_cast<uint4*>(As + row * LDS_STRIDE + c4) = t;
        }
#pragma unroll
        for (int l = 0; l < 4; l++) {
            int idx = tid + l * 256;
            int n  = idx >> 3;
            int c4 = (idx & 7) * 4;
            float4 v = *reinterpret_cast<const float4*>(WT + (size_t)n * IN_DIM + k0 + c4);
            uint4 t = make_uint4(f2tf32(v.x), f2tf32(v.y), f2tf32(v.z), f2tf32(v.w));
            *reinterpret_cast<uint4*>(Bs + n * LDS_STRIDE + c4) = t;
        }
        __syncthreads();

#pragma unroll
        for (int kk = 0; kk < 32; kk += 8) {
            uint32_t a[2][4];
#pragma unroll
            for (int mt = 0; mt < 2; mt++) {
                int r = mw * 32 + mt * 16 + qr;
                a[mt][0] = As[r * LDS_STRIDE + kk + qc];
                a[mt][1] = As[(r + 8) * LDS_STRIDE + kk + qc];
                a[mt][2] = As[r * LDS_STRIDE + kk + qc + 4];
                a[mt][3] = As[(r + 8) * LDS_STRIDE + kk + qc + 4];
            }
            uint32_t b[8][2];
#pragma unroll
            for (int nt = 0; nt < 8; nt++) {
                int c = nw * 64 + nt * 8 + qr;
                b[nt][0] = Bs[c * LDS_STRIDE + kk + qc];
                b[nt][1] = Bs[c * LDS_STRIDE + kk + qc + 4];
            }
#pragma unroll
            for (int mt = 0; mt < 2; mt++)
#pragma unroll
                for (int nt = 0; nt < 8; nt++) {
                    asm volatile(
                        "mma.sync.aligned.m16n8k8.row.col.f32.tf32.tf32.f32 "
                        "{%0,%1,%2,%3}, {%4,%5,%6,%7}, {%8,%9}, {%0,%1,%2,%3};"
                        : "+f"(acc[mt][nt][0]), "+f"(acc[mt][nt][1]),
                          "+f"(acc[mt][nt][2]), "+f"(acc[mt][nt][3])
                        : "r"(a[mt][0]), "r"(a[mt][1]), "r"(a[mt][2]), "r"(a[mt][3]),
                          "r"(b[nt][0]), "r"(b[nt][1]));
                }
        }
        __syncthreads();
    }

#pragma unroll
    for (int mt = 0; mt < 2; mt++) {
        int r0 = rowBase + mw * 32 + mt * 16 + qr;
        int r1 = r0 + 8;
#pragma unroll
        for (int nt = 0; nt < 8; nt++) {
            int c = nw * 64 + nt * 8 + qc * 2;
            if (r0 < N) {
                __half2 h01 = __floats2half2_rn(acc[mt][nt][0], acc[mt][nt][1]);
                *reinterpret_cast<__half2*>(Hh + (size_t)r0 * OUT_DIM + c) = h01;
            }
            if (r1 < N) {
                __half2 h23 = __floats2half2_rn(acc[mt][nt][2], acc[mt][nt][3]);
                *reinterpret_cast<__half2*>(Hh + (size_t)r1 * OUT_DIM + c) = h23;
            }
        }
    }
}

// ---------------------------------------------------------------------------
// CSR build: memset -> histogram(x4) -> scan -> permute(x2, emits dst too)
// ---------------------------------------------------------------------------
__global__ void hist_kernel(const int* __restrict__ dst, int* __restrict__ deg, int E)
{
    int i = (blockIdx.x * blockDim.x + threadIdx.x) * 4;
    if (i + 3 < E) {
        int4 d = *reinterpret_cast<const int4*>(dst + i);
        atomicAdd(&deg[d.x], 1);
        atomicAdd(&deg[d.y], 1);
        atomicAdd(&deg[d.z], 1);
        atomicAdd(&deg[d.w], 1);
    } else {
        for (int e = i; e < E; e++) atomicAdd(&deg[dst[e]], 1);
    }
}

__global__ __launch_bounds__(1024) void scan1_kernel(
    const int* __restrict__ deg, int* __restrict__ partial,
    int* __restrict__ bsum, int n)
{
    __shared__ int sh[1024];
    int gid = blockIdx.x * 1024 + threadIdx.x;
    int v = (gid < n) ? deg[gid] : 0;
    sh[threadIdx.x] = v;
    __syncthreads();
#pragma unroll
    for (int off = 1; off < 1024; off <<= 1) {
        int t = (threadIdx.x >= off) ? sh[threadIdx.x - off] : 0;
        __syncthreads();
        sh[threadIdx.x] += t;
        __syncthreads();
    }
    if (gid < n) partial[gid] = sh[threadIdx.x] - v;
    if (threadIdx.x == 1023) bsum[blockIdx.x] = sh[1023];
}

__global__ __launch_bounds__(32) void scan2_kernel(int* __restrict__ bsum, int nb)
{
    int lane = threadIdx.x;
    int v[4];
#pragma unroll
    for (int j = 0; j < 4; j++) {
        int idx = lane * 4 + j;
        v[j] = (idx < nb) ? bsum[idx] : 0;
    }
    int local = v[0] + v[1] + v[2] + v[3];
    int pre = local;
#pragma unroll
    for (int off = 1; off < 32; off <<= 1) {
        int t = __shfl_up_sync(0xffffffffu, pre, off);
        if (lane >= off) pre += t;
    }
    int run = pre - local;
#pragma unroll
    for (int j = 0; j < 4; j++) {
        int idx = lane * 4 + j;
        if (idx < nb) bsum[idx] = run;
        run += v[j];
    }
}

__global__ void scan3_kernel(int* __restrict__ rowptr, int* __restrict__ fill,
                             const int* __restrict__ bsum, int n, int E)
{
    int gid = blockIdx.x * blockDim.x + threadIdx.x;
    if (gid < n) {
        int v = rowptr[gid] + bsum[gid >> 10];
        rowptr[gid] = v;
        fill[gid] = v;
    }
    if (gid == 0) rowptr[n] = E;
}

__global__ void permute_kernel(
    const int* __restrict__ src, const int* __restrict__ dst,
    const float* __restrict__ val, int* __restrict__ fill,
    int2* __restrict__ es, int* __restrict__ dss, int E)
{
    int i = (blockIdx.x * blockDim.x + threadIdx.x) * 2;
    if (i + 1 < E) {
        int2   s = *reinterpret_cast<const int2*>(src + i);
        int2   d = *reinterpret_cast<const int2*>(dst + i);
        float2 v = *reinterpret_cast<const float2*>(val + i);
        int p0 = atomicAdd(&fill[d.x], 1);
        int p1 = atomicAdd(&fill[d.y], 1);
        __stcs(es + p0, make_int2(s.x, __float_as_int(v.x)));
        __stcs(es + p1, make_int2(s.y, __float_as_int(v.y)));
        __stcs(dss + p0, d.x);
        __stcs(dss + p1, d.y);
    } else if (i < E) {
        int d = dst[i];
        int p = atomicAdd(&fill[d], 1);
        __stcs(es + p, make_int2(src[i], __float_as_int(val[i])));
        __stcs(dss + p, d);
    }
}

// ---------------------------------------------------------------------------
// out = bias (broadcast) — baseline for RED accumulation, covers deg-0 nodes.
// ---------------------------------------------------------------------------
__global__ void init_out_kernel(float4* __restrict__ out4,
                                const float4* __restrict__ b4, int n4)
{
    int i = blockIdx.x * blockDim.x + threadIdx.x;
    if (i < n4) out4[i] = b4[i & 31];
}

// ---------------------------------------------------------------------------
// Edge-parallel gather: each warp owns 32 consecutive dst-sorted edges.
// Perfect load balance; es/dst loads are contiguous broadcasts; 8 h-row
// loads in flight per batch; register accumulation across same-dst runs;
// dst transitions flushed with red.global.add.v4.f32 (fire-and-forget).
// ---------------------------------------------------------------------------
__device__ __forceinline__ void hfma4(float4& acc, uint2 q, float v)
{
    __half2 a = *reinterpret_cast<__half2*>(&q.x);
    __half2 b = *reinterpret_cast<__half2*>(&q.y);
    float2 fa = __half22float2(a);
    float2 fb = __half22float2(b);
    acc.x = fmaf(fa.x, v, acc.x); acc.y = fmaf(fa.y, v, acc.y);
    acc.z = fmaf(fb.x, v, acc.z); acc.w = fmaf(fb.y, v, acc.w);
}

__device__ __forceinline__ void red_add4(float* p, float4 a)
{
    asm volatile("red.global.add.v4.f32 [%0], {%1, %2, %3, %4};"
                 :: "l"(p), "f"(a.x), "f"(a.y), "f"(a.z), "f"(a.w) : "memory");
}

__global__ __launch_bounds__(256) void gather_kernel(
    const __half* __restrict__ h, const int2* __restrict__ es,
    const int* __restrict__ dss, float* __restrict__ out, int E)
{
    const int lane = threadIdx.x & 31;
    const int warp = (blockIdx.x * blockDim.x + threadIdx.x) >> 5;
    const int col4 = lane * 4;

    int e = warp * 32;
    if (e >= E) return;
    const int eend = (e + 32 < E) ? e + 32 : E;

    float4 acc = make_float4(0.f, 0.f, 0.f, 0.f);
    int cur = __ldg(dss + e);

    while (e + 8 <= eend) {
        int  dd[8];
        int2 ev[8];
        uint2 q[8];
#pragma unroll
        for (int j = 0; j < 8; j++) dd[j] = __ldg(dss + e + j);
#pragma unroll
        for (int j = 0; j < 8; j++) ev[j] = __ldg(es + e + j);
#pragma unroll
        for (int j = 0; j < 8; j++)
            q[j] = *reinterpret_cast<const uint2*>(h + (size_t)ev[j].x * OUT_DIM + col4);
#pragma unroll
        for (int j = 0; j < 8; j++) {
            if (dd[j] != cur) {
                red_add4(out + (size_t)cur * OUT_DIM + col4, acc);
                acc = make_float4(0.f, 0.f, 0.f, 0.f);
                cur = dd[j];
            }
            hfma4(acc, q[j], __int_as_float(ev[j].y));
        }
        e += 8;
    }
    for (; e < eend; e++) {
        int d = __ldg(dss + e);
        int2 ev = __ldg(es + e);
        uint2 q = *reinterpret_cast<const uint2*>(h + (size_t)ev.x * OUT_DIM + col4);
        if (d != cur) {
            red_add4(out + (size_t)cur * OUT_DIM + col4, acc);
            acc = make_float4(0.f, 0.f, 0.f, 0.f);
            cur = d;
        }
        hfma4(acc, q, __int_as_float(ev.y));
    }
    red_add4(out + (size_t)cur * OUT_DIM + col4, acc);
}

// ---------------------------------------------------------------------------
// Launch: side = CSR build; C = out-init; main = transpose -> gemm -> gather.
// ---------------------------------------------------------------------------
extern "C" void kernel_launch(void* const* d_in, const int* in_sizes, int n_in,
                              void* d_out, int out_size)
{
    const float* X    = (const float*)d_in[0];   // [N, 256]
    const int*   src  = (const int*)  d_in[1];   // [E]
    const int*   dst  = (const int*)  d_in[2];   // [E]
    const float* vals = (const float*)d_in[3];   // [E]
    const float* W    = (const float*)d_in[4];   // [256, 128]
    const float* b    = (const float*)d_in[5];   // [128]
    float* out = (float*)d_out;                  // [N, 128]

    const int N = in_sizes[0] / IN_DIM;
    const int E = in_sizes[1];

    __half* Hh;     cudaGetSymbolAddress((void**)&Hh,      g_hh);
    float*  WT;     cudaGetSymbolAddress((void**)&WT,      g_wt);
    int*    deg;    cudaGetSymbolAddress((void**)&deg,     g_deg);
    int*    rowptr; cudaGetSymbolAddress((void**)&rowptr,  g_rowptr);
    int*    fill;   cudaGetSymbolAddress((void**)&fill,    g_fill);
    int*    bsum;   cudaGetSymbolAddress((void**)&bsum,    g_bsum);
    int2*   es;     cudaGetSymbolAddress((void**)&es,      g_esorted);
    int*    dss;    cudaGetSymbolAddress((void**)&dss,     g_dsorted);

    const int nb = (N + 1023) / 1024;

    static cudaStream_t s_side = nullptr, s_init = nullptr;
    static cudaEvent_t  e_fork = nullptr, e_join = nullptr, e_init = nullptr;
    if (s_side == nullptr) {
        cudaStreamCreateWithFlags(&s_side, cudaStreamNonBlocking);
        cudaStreamCreateWithFlags(&s_init, cudaStreamNonBlocking);
        cudaEventCreateWithFlags(&e_fork, cudaEventDisableTiming);
        cudaEventCreateWithFlags(&e_join, cudaEventDisableTiming);
        cudaEventCreateWithFlags(&e_init, cudaEventDisableTiming);
    }

    // Fork side streams.
    cudaEventRecord(e_fork, 0);
    cudaStreamWaitEvent(s_side, e_fork, 0);
    cudaStreamWaitEvent(s_init, e_fork, 0);

    // Side: zero degrees (memset node), histogram, first scan stage.
    cudaMemsetAsync(deg, 0, (size_t)N * sizeof(int), s_side);
    hist_kernel<<<(E / 4 + 255) / 256, 256, 0, s_side>>>(dst, deg, E);      // k0
    scan1_kernel<<<nb, 1024, 0, s_side>>>(deg, rowptr, bsum, N);            // k1

    // Main: transpose, then GEMM (kernel launch index 3 -> ncu target).
    transpose_w_kernel<<<(IN_DIM * OUT_DIM + 255) / 256, 256>>>(W, WT);     // k2
    gemm_mma_kernel<<<(N + 127) / 128, 256>>>(X, WT, Hh, N);                // k3

    // Init stream: out = bias broadcast.
    {
        int n4 = N * (OUT_DIM / 4);
        init_out_kernel<<<(n4 + 255) / 256, 256, 0, s_init>>>(
            (float4*)out, (const float4*)b, n4);                            // k4
        cudaEventRecord(e_init, s_init);
    }

    // Side: rest of the build.
    scan2_kernel<<<1, 32, 0, s_side>>>(bsum, nb);                           // k5
    scan3_kernel<<<(N + 255) / 256, 256, 0, s_side>>>(rowptr, fill, bsum, N, E); // k6
    permute_kernel<<<(E / 2 + 255) / 256, 256, 0, s_side>>>(src, dst, vals, fill, es, dss, E); // k7
    cudaEventRecord(e_join, s_side);

    // Join everything, then edge-parallel gather.
    cudaStreamWaitEvent(0, e_join, 0);
    cudaStreamWaitEvent(0, e_init, 0);
    {
        int nwarps = (E + 31) / 32;
        int nthreads = nwarps * 32;
        gather_kernel<<<(nthreads + 255) / 256, 256>>>(Hh, es, dss, out, E); // k8
    }
}

// round 12
// speedup vs baseline: 1.5680x; 1.5680x over previous
#include <cuda_runtime.h>
#include <cuda_fp16.h>
#include <cstdint>

#define IN_DIM    256
#define OUT_DIM   128
#define MAX_NODES 100000
#define MAX_EDGES 3200000

// ---------------- device scratch (static, no allocation) -------------------
__device__ __half g_hh[MAX_NODES * OUT_DIM];      // h = X @ W in fp16
__device__ int    g_deg[MAX_NODES];
__device__ int    g_rowptr[MAX_NODES + 1];
__device__ int    g_fill[MAX_NODES];
__device__ int    g_bsum[128];
__device__ int2   g_esorted[MAX_EDGES];           // (src, val_bits) sorted by dst

// ---------------------------------------------------------------------------
// GEMM via mma.sync tf32 (round-6 structure: best measured, 57.7us).
// BM=128, BN=128, BK=32; 8 warps (4m x 2n); warp tile 32x64 (2x8 m16n8k8).
// B tile loaded DIRECTLY from W[k][n] (coalesced over n) — no transpose
// kernel, no WT buffer.  Output stored fp16.
// ---------------------------------------------------------------------------
#define LDS_STRIDE 36   // 32 + 4 pad: frag LDS conflict-free, 16B-aligned rows

__device__ __forceinline__ uint32_t f2tf32(float f) {
    uint32_t r;
    asm("cvt.rna.tf32.f32 %0, %1;" : "=r"(r) : "f"(f));
    return r;
}

__global__ __launch_bounds__(256) void gemm_mma_kernel(
    const float* __restrict__ X, const float* __restrict__ W,
    __half* __restrict__ Hh, int N)
{
    __shared__ uint32_t As[128 * LDS_STRIDE];   // [m][k] tf32 bits
    __shared__ uint32_t Bs[128 * LDS_STRIDE];   // [n][k] tf32 bits

    const int tid  = threadIdx.x;
    const int wid  = tid >> 5;
    const int lane = tid & 31;
    const int mw   = wid >> 1;        // 0..3
    const int nw   = wid & 1;         // 0..1
    const int rowBase = blockIdx.x * 128;

    const int qr = lane >> 2;         // 0..7
    const int qc = lane & 3;          // 0..3

    float acc[2][8][4];
#pragma unroll
    for (int mt = 0; mt < 2; mt++)
#pragma unroll
        for (int nt = 0; nt < 8; nt++)
#pragma unroll
            for (int j = 0; j < 4; j++) acc[mt][nt][j] = 0.0f;

    for (int k0 = 0; k0 < IN_DIM; k0 += 32) {
        // --- A tile: 128 rows x 32 k (float4 loads), cvt tf32 at store ---
#pragma unroll
        for (int l = 0; l < 4; l++) {
            int idx = tid + l * 256;            // 0..1023
            int row = idx >> 3;
            int c4  = (idx & 7) * 4;
            float4 v;
            int grow = rowBase + row;
            if (grow < N)
                v = *reinterpret_cast<const float4*>(X + (size_t)grow * IN_DIM + k0 + c4);
            else
                v = make_float4(0.f, 0.f, 0.f, 0.f);
            uint4 t = make_uint4(f2tf32(v.x), f2tf32(v.y), f2tf32(v.z), f2tf32(v.w));
            *reinterpret_cast<uint4*>(As + row * LDS_STRIDE + c4) = t;
        }
        // --- B tile: read W[k0+k][n] coalesced (n contiguous), store
        //     transposed into Bs[n][k].  32k x 128n = 4096 scalars. ---
#pragma unroll
        for (int l = 0; l < 16; l++) {
            int idx = tid + l * 256;            // 0..4095
            int k = idx >> 7;                   // 0..31
            int n = idx & 127;                  // 0..127
            float w = __ldg(W + (size_t)(k0 + k) * OUT_DIM + n);
            Bs[n * LDS_STRIDE + k] = f2tf32(w);
        }
        __syncthreads();

#pragma unroll
        for (int kk = 0; kk < 32; kk += 8) {
            uint32_t a[2][4];
#pragma unroll
            for (int mt = 0; mt < 2; mt++) {
                int r = mw * 32 + mt * 16 + qr;
                a[mt][0] = As[r * LDS_STRIDE + kk + qc];
                a[mt][1] = As[(r + 8) * LDS_STRIDE + kk + qc];
                a[mt][2] = As[r * LDS_STRIDE + kk + qc + 4];
                a[mt][3] = As[(r + 8) * LDS_STRIDE + kk + qc + 4];
            }
            uint32_t b[8][2];
#pragma unroll
            for (int nt = 0; nt < 8; nt++) {
                int c = nw * 64 + nt * 8 + qr;
                b[nt][0] = Bs[c * LDS_STRIDE + kk + qc];
                b[nt][1] = Bs[c * LDS_STRIDE + kk + qc + 4];
            }
#pragma unroll
            for (int mt = 0; mt < 2; mt++)
#pragma unroll
                for (int nt = 0; nt < 8; nt++) {
                    asm volatile(
                        "mma.sync.aligned.m16n8k8.row.col.f32.tf32.tf32.f32 "
                        "{%0,%1,%2,%3}, {%4,%5,%6,%7}, {%8,%9}, {%0,%1,%2,%3};"
                        : "+f"(acc[mt][nt][0]), "+f"(acc[mt][nt][1]),
                          "+f"(acc[mt][nt][2]), "+f"(acc[mt][nt][3])
                        : "r"(a[mt][0]), "r"(a[mt][1]), "r"(a[mt][2]), "r"(a[mt][3]),
                          "r"(b[nt][0]), "r"(b[nt][1]));
                }
        }
        __syncthreads();
    }

#pragma unroll
    for (int mt = 0; mt < 2; mt++) {
        int r0 = rowBase + mw * 32 + mt * 16 + qr;
        int r1 = r0 + 8;
#pragma unroll
        for (int nt = 0; nt < 8; nt++) {
            int c = nw * 64 + nt * 8 + qc * 2;
            if (r0 < N) {
                __half2 h01 = __floats2half2_rn(acc[mt][nt][0], acc[mt][nt][1]);
                *reinterpret_cast<__half2*>(Hh + (size_t)r0 * OUT_DIM + c) = h01;
            }
            if (r1 < N) {
                __half2 h23 = __floats2half2_rn(acc[mt][nt][2], acc[mt][nt][3]);
                *reinterpret_cast<__half2*>(Hh + (size_t)r1 * OUT_DIM + c) = h23;
            }
        }
    }
}

// ---------------------------------------------------------------------------
// CSR build: memset -> histogram(x4) -> scan -> permute(x2)
// ---------------------------------------------------------------------------
__global__ void hist_kernel(const int* __restrict__ dst, int* __restrict__ deg, int E)
{
    int i = (blockIdx.x * blockDim.x + threadIdx.x) * 4;
    if (i + 3 < E) {
        int4 d = *reinterpret_cast<const int4*>(dst + i);
        atomicAdd(&deg[d.x], 1);
        atomicAdd(&deg[d.y], 1);
        atomicAdd(&deg[d.z], 1);
        atomicAdd(&deg[d.w], 1);
    } else {
        for (int e = i; e < E; e++) atomicAdd(&deg[dst[e]], 1);
    }
}

__global__ __launch_bounds__(1024) void scan1_kernel(
    const int* __restrict__ deg, int* __restrict__ partial,
    int* __restrict__ bsum, int n)
{
    __shared__ int sh[1024];
    int gid = blockIdx.x * 1024 + threadIdx.x;
    int v = (gid < n) ? deg[gid] : 0;
    sh[threadIdx.x] = v;
    __syncthreads();
#pragma unroll
    for (int off = 1; off < 1024; off <<= 1) {
        int t = (threadIdx.x >= off) ? sh[threadIdx.x - off] : 0;
        __syncthreads();
        sh[threadIdx.x] += t;
        __syncthreads();
    }
    if (gid < n) partial[gid] = sh[threadIdx.x] - v;
    if (threadIdx.x == 1023) bsum[blockIdx.x] = sh[1023];
}

// single-warp shuffle scan over <=128 block sums
__global__ __launch_bounds__(32) void scan2_kernel(int* __restrict__ bsum, int nb)
{
    int lane = threadIdx.x;
    int v[4];
#pragma unroll
    for (int j = 0; j < 4; j++) {
        int idx = lane * 4 + j;
        v[j] = (idx < nb) ? bsum[idx] : 0;
    }
    int local = v[0] + v[1] + v[2] + v[3];
    int pre = local;
#pragma unroll
    for (int off = 1; off < 32; off <<= 1) {
        int t = __shfl_up_sync(0xffffffffu, pre, off);
        if (lane >= off) pre += t;
    }
    int run = pre - local;
#pragma unroll
    for (int j = 0; j < 4; j++) {
        int idx = lane * 4 + j;
        if (idx < nb) bsum[idx] = run;
        run += v[j];
    }
}

__global__ void scan3_kernel(int* __restrict__ rowptr, int* __restrict__ fill,
                             const int* __restrict__ bsum, int n, int E)
{
    int gid = blockIdx.x * blockDim.x + threadIdx.x;
    if (gid < n) {
        int v = rowptr[gid] + bsum[gid >> 10];
        rowptr[gid] = v;
        fill[gid] = v;
    }
    if (gid == 0) rowptr[n] = E;
}

__global__ void permute_kernel(
    const int* __restrict__ src, const int* __restrict__ dst,
    const float* __restrict__ val, int* __restrict__ fill,
    int2* __restrict__ es, int E)
{
    int i = (blockIdx.x * blockDim.x + threadIdx.x) * 2;
    if (i + 1 < E) {
        int2   s = *reinterpret_cast<const int2*>(src + i);
        int2   d = *reinterpret_cast<const int2*>(dst + i);
        float2 v = *reinterpret_cast<const float2*>(val + i);
        int p0 = atomicAdd(&fill[d.x], 1);
        int p1 = atomicAdd(&fill[d.y], 1);
        __stcs(es + p0, make_int2(s.x, __float_as_int(v.x)));
        __stcs(es + p1, make_int2(s.y, __float_as_int(v.y)));
    } else if (i < E) {
        int p = atomicAdd(&fill[dst[i]], 1);
        __stcs(es + p, make_int2(src[i], __float_as_int(val[i])));
    }
}

// ---------------------------------------------------------------------------
// Gather from fp16 h (round-6 version: best measured).
// One warp per dst node, 8-deep pipeline, __ldcs es, __stcs out, fused bias.
// ---------------------------------------------------------------------------
__device__ __forceinline__ void hfma4(float4& acc, uint2 q, float v)
{
    __half2 a = *reinterpret_cast<__half2*>(&q.x);
    __half2 b = *reinterpret_cast<__half2*>(&q.y);
    float2 fa = __half22float2(a);
    float2 fb = __half22float2(b);
    acc.x = fmaf(fa.x, v, acc.x); acc.y = fmaf(fa.y, v, acc.y);
    acc.z = fmaf(fb.x, v, acc.z); acc.w = fmaf(fb.y, v, acc.w);
}

__global__ __launch_bounds__(256) void gather_kernel(
    const __half* __restrict__ h, const int* __restrict__ rowptr,
    const int2* __restrict__ es, const float* __restrict__ bias,
    float* __restrict__ out, int N)
{
    const int lane = threadIdx.x & 31;
    const int warp = (blockIdx.x * blockDim.x + threadIdx.x) >> 5;
    const int nw   = (gridDim.x * blockDim.x) >> 5;

    const float4 bv = *reinterpret_cast<const float4*>(bias + lane * 4);
    const int col4 = lane * 4;

    for (int d = warp; d < N; d += nw) {
        const int beg = rowptr[d];
        const int end = rowptr[d + 1];
        float4 acc = bv;

        int e = beg;
        for (; e + 7 < end; e += 8) {
            int2 ev[8];
#pragma unroll
            for (int j = 0; j < 8; j++) ev[j] = __ldcs(es + e + j);
            uint2 q[8];
#pragma unroll
            for (int j = 0; j < 8; j++)
                q[j] = *reinterpret_cast<const uint2*>(h + (size_t)ev[j].x * OUT_DIM + col4);
#pragma unroll
            for (int j = 0; j < 8; j++) hfma4(acc, q[j], __int_as_float(ev[j].y));
        }
        for (; e < end; e++) {
            const int2 ev = __ldcs(es + e);
            uint2 q = *reinterpret_cast<const uint2*>(h + (size_t)ev.x * OUT_DIM + col4);
            hfma4(acc, q, __int_as_float(ev.y));
        }
        __stcs(reinterpret_cast<float4*>(out + (size_t)d * OUT_DIM + col4), acc);
    }
}

// ---------------------------------------------------------------------------
// Launch: side = CSR build, main = gemm (launch idx 3) -> gather.
// ---------------------------------------------------------------------------
extern "C" void kernel_launch(void* const* d_in, const int* in_sizes, int n_in,
                              void* d_out, int out_size)
{
    const float* X    = (const float*)d_in[0];   // [N, 256]
    const int*   src  = (const int*)  d_in[1];   // [E]
    const int*   dst  = (const int*)  d_in[2];   // [E]
    const float* vals = (const float*)d_in[3];   // [E]
    const float* W    = (const float*)d_in[4];   // [256, 128]
    const float* b    = (const float*)d_in[5];   // [128]
    float* out = (float*)d_out;                  // [N, 128]

    const int N = in_sizes[0] / IN_DIM;
    const int E = in_sizes[1];

    __half* Hh;     cudaGetSymbolAddress((void**)&Hh,      g_hh);
    int*    deg;    cudaGetSymbolAddress((void**)&deg,     g_deg);
    int*    rowptr; cudaGetSymbolAddress((void**)&rowptr,  g_rowptr);
    int*    fill;   cudaGetSymbolAddress((void**)&fill,    g_fill);
    int*    bsum;   cudaGetSymbolAddress((void**)&bsum,    g_bsum);
    int2*   es;     cudaGetSymbolAddress((void**)&es,      g_esorted);

    const int nb = (N + 1023) / 1024;

    static cudaStream_t s_side = nullptr;
    static cudaEvent_t  e_fork = nullptr, e_join = nullptr;
    if (s_side == nullptr) {
        cudaStreamCreateWithFlags(&s_side, cudaStreamNonBlocking);
        cudaEventCreateWithFlags(&e_fork, cudaEventDisableTiming);
        cudaEventCreateWithFlags(&e_join, cudaEventDisableTiming);
    }

    // Fork side stream.
    cudaEventRecord(e_fork, 0);
    cudaStreamWaitEvent(s_side, e_fork, 0);

    // Side: zero degrees (memset node), histogram, scans.
    cudaMemsetAsync(deg, 0, (size_t)N * sizeof(int), s_side);
    hist_kernel<<<(E / 4 + 255) / 256, 256, 0, s_side>>>(dst, deg, E);      // k0
    scan1_kernel<<<nb, 1024, 0, s_side>>>(deg, rowptr, bsum, N);            // k1
    scan2_kernel<<<1, 32, 0, s_side>>>(bsum, nb);                           // k2

    // Main: GEMM h = X @ W (kernel launch index 3 -> ncu target).
    gemm_mma_kernel<<<(N + 127) / 128, 256>>>(X, W, Hh, N);                 // k3

    // Side: rest of the build.
    scan3_kernel<<<(N + 255) / 256, 256, 0, s_side>>>(rowptr, fill, bsum, N, E); // k4
    permute_kernel<<<(E / 2 + 255) / 256, 256, 0, s_side>>>(src, dst, vals, fill, es, E); // k5
    cudaEventRecord(e_join, s_side);

    // Join, then gather with fused bias.
    cudaStreamWaitEvent(0, e_join, 0);
    gather_kernel<<<(N * 32 + 255) / 256, 256>>>(Hh, rowptr, es, b, out, N); // k6
}

// round 15
// speedup vs baseline: 1.6627x; 1.0604x over previous
#include <cuda_runtime.h>
#include <cuda_fp16.h>
#include <cstdint>

#define IN_DIM    256
#define OUT_DIM   128
#define MAX_NODES 100000
#define MAX_EDGES 3200000

// ---------------- device scratch (static, no allocation) -------------------
__device__ __half   g_hh[MAX_NODES * OUT_DIM];    // h = X @ W in fp16
__device__ uint32_t g_wt[OUT_DIM * IN_DIM];       // W^T pre-converted tf32 bits
__device__ int      g_deg[MAX_NODES];
__device__ int      g_rowptr[MAX_NODES + 1];
__device__ int      g_fill[MAX_NODES];
__device__ int      g_bsum[128];
__device__ int2     g_esorted[MAX_EDGES];         // (src, val_bits) sorted by dst

__device__ __forceinline__ uint32_t f2tf32(float f) {
    uint32_t r;
    asm("cvt.rna.tf32.f32 %0, %1;" : "=r"(r) : "f"(f));
    return r;
}

// ---------------------------------------------------------------------------
// W transpose + tf32 pre-convert: WT[n][k] = tf32(W[k][n])
// ---------------------------------------------------------------------------
__global__ void transpose_w_kernel(const float* __restrict__ W, uint32_t* __restrict__ WT)
{
    int i = blockIdx.x * blockDim.x + threadIdx.x;
    if (i < IN_DIM * OUT_DIM) {
        int k = i / OUT_DIM, n = i % OUT_DIM;
        WT[n * IN_DIM + k] = f2tf32(W[i]);
    }
}

// ---------------------------------------------------------------------------
// GEMM via mma.sync tf32 (round-6 structure: best measured, 57.7us).
// BM=128, BN=128, BK=32; 8 warps (4m x 2n); warp tile 32x64 (2x8 m16n8k8).
// B tiles are pre-converted tf32 bits (no cvt in B path).  Output fp16.
// ---------------------------------------------------------------------------
#define LDS_STRIDE 36   // 32 + 4 pad: frag LDS conflict-free, 16B-aligned rows

__global__ __launch_bounds__(256) void gemm_mma_kernel(
    const float* __restrict__ X, const uint32_t* __restrict__ WT,
    __half* __restrict__ Hh, int N)
{
    __shared__ uint32_t As[128 * LDS_STRIDE];   // [m][k] tf32 bits
    __shared__ uint32_t Bs[128 * LDS_STRIDE];   // [n][k] tf32 bits

    const int tid  = threadIdx.x;
    const int wid  = tid >> 5;
    const int lane = tid & 31;
    const int mw   = wid >> 1;        // 0..3
    const int nw   = wid & 1;         // 0..1
    const int rowBase = blockIdx.x * 128;

    const int qr = lane >> 2;         // 0..7
    const int qc = lane & 3;          // 0..3

    float acc[2][8][4];
#pragma unroll
    for (int mt = 0; mt < 2; mt++)
#pragma unroll
        for (int nt = 0; nt < 8; nt++)
#pragma unroll
            for (int j = 0; j < 4; j++) acc[mt][nt][j] = 0.0f;

    for (int k0 = 0; k0 < IN_DIM; k0 += 32) {
        // --- A tile: 128 rows x 32 k, cvt tf32 at store ---
#pragma unroll
        for (int l = 0; l < 4; l++) {
            int idx = tid + l * 256;            // 0..1023
            int row = idx >> 3;
            int c4  = (idx & 7) * 4;
            float4 v;
            int grow = rowBase + row;
            if (grow < N)
                v = *reinterpret_cast<const float4*>(X + (size_t)grow * IN_DIM + k0 + c4);
            else
                v = make_float4(0.f, 0.f, 0.f, 0.f);
            uint4 t = make_uint4(f2tf32(v.x), f2tf32(v.y), f2tf32(v.z), f2tf32(v.w));
            *reinterpret_cast<uint4*>(As + row * LDS_STRIDE + c4) = t;
        }
        // --- B tile: 128 n x 32 k, raw tf32 bits (uint4 loads, no cvt) ---
#pragma unroll
        for (int l = 0; l < 4; l++) {
            int idx = tid + l * 256;
            int n  = idx >> 3;
            int c4 = (idx & 7) * 4;
            uint4 t = *reinterpret_cast<const uint4*>(WT + (size_t)n * IN_DIM + k0 + c4);
            *reinterpret_cast<uint4*>(Bs + n * LDS_STRIDE + c4) = t;
        }
        __syncthreads();

#pragma unroll
        for (int kk = 0; kk < 32; kk += 8) {
            uint32_t a[2][4];
#pragma unroll
            for (int mt = 0; mt < 2; mt++) {
                int r = mw * 32 + mt * 16 + qr;
                a[mt][0] = As[r * LDS_STRIDE + kk + qc];
                a[mt][1] = As[(r + 8) * LDS_STRIDE + kk + qc];
                a[mt][2] = As[r * LDS_STRIDE + kk + qc + 4];
                a[mt][3] = As[(r + 8) * LDS_STRIDE + kk + qc + 4];
            }
            uint32_t b[8][2];
#pragma unroll
            for (int nt = 0; nt < 8; nt++) {
                int c = nw * 64 + nt * 8 + qr;
                b[nt][0] = Bs[c * LDS_STRIDE + kk + qc];
                b[nt][1] = Bs[c * LDS_STRIDE + kk + qc + 4];
            }
#pragma unroll
            for (int mt = 0; mt < 2; mt++)
#pragma unroll
                for (int nt = 0; nt < 8; nt++) {
                    asm volatile(
                        "mma.sync.aligned.m16n8k8.row.col.f32.tf32.tf32.f32 "
                        "{%0,%1,%2,%3}, {%4,%5,%6,%7}, {%8,%9}, {%0,%1,%2,%3};"
                        : "+f"(acc[mt][nt][0]), "+f"(acc[mt][nt][1]),
                          "+f"(acc[mt][nt][2]), "+f"(acc[mt][nt][3])
                        : "r"(a[mt][0]), "r"(a[mt][1]), "r"(a[mt][2]), "r"(a[mt][3]),
                          "r"(b[nt][0]), "r"(b[nt][1]));
                }
        }
        __syncthreads();
    }

#pragma unroll
    for (int mt = 0; mt < 2; mt++) {
        int r0 = rowBase + mw * 32 + mt * 16 + qr;
        int r1 = r0 + 8;
#pragma unroll
        for (int nt = 0; nt < 8; nt++) {
            int c = nw * 64 + nt * 8 + qc * 2;
            if (r0 < N) {
                __half2 h01 = __floats2half2_rn(acc[mt][nt][0], acc[mt][nt][1]);
                *reinterpret_cast<__half2*>(Hh + (size_t)r0 * OUT_DIM + c) = h01;
            }
            if (r1 < N) {
                __half2 h23 = __floats2half2_rn(acc[mt][nt][2], acc[mt][nt][3]);
                *reinterpret_cast<__half2*>(Hh + (size_t)r1 * OUT_DIM + c) = h23;
            }
        }
    }
}

// ---------------------------------------------------------------------------
// CSR build: memset -> histogram(x4) -> scan -> permute(x2)
// ---------------------------------------------------------------------------
__global__ void hist_kernel(const int* __restrict__ dst, int* __restrict__ deg, int E)
{
    int i = (blockIdx.x * blockDim.x + threadIdx.x) * 4;
    if (i + 3 < E) {
        int4 d = *reinterpret_cast<const int4*>(dst + i);
        atomicAdd(&deg[d.x], 1);
        atomicAdd(&deg[d.y], 1);
        atomicAdd(&deg[d.z], 1);
        atomicAdd(&deg[d.w], 1);
    } else {
        for (int e = i; e < E; e++) atomicAdd(&deg[dst[e]], 1);
    }
}

__global__ __launch_bounds__(1024) void scan1_kernel(
    const int* __restrict__ deg, int* __restrict__ partial,
    int* __restrict__ bsum, int n)
{
    __shared__ int sh[1024];
    int gid = blockIdx.x * 1024 + threadIdx.x;
    int v = (gid < n) ? deg[gid] : 0;
    sh[threadIdx.x] = v;
    __syncthreads();
#pragma unroll
    for (int off = 1; off < 1024; off <<= 1) {
        int t = (threadIdx.x >= off) ? sh[threadIdx.x - off] : 0;
        __syncthreads();
        sh[threadIdx.x] += t;
        __syncthreads();
    }
    if (gid < n) partial[gid] = sh[threadIdx.x] - v;
    if (threadIdx.x == 1023) bsum[blockIdx.x] = sh[1023];
}

// single-warp shuffle scan over <=128 block sums
__global__ __launch_bounds__(32) void scan2_kernel(int* __restrict__ bsum, int nb)
{
    int lane = threadIdx.x;
    int v[4];
#pragma unroll
    for (int j = 0; j < 4; j++) {
        int idx = lane * 4 + j;
        v[j] = (idx < nb) ? bsum[idx] : 0;
    }
    int local = v[0] + v[1] + v[2] + v[3];
    int pre = local;
#pragma unroll
    for (int off = 1; off < 32; off <<= 1) {
        int t = __shfl_up_sync(0xffffffffu, pre, off);
        if (lane >= off) pre += t;
    }
    int run = pre - local;
#pragma unroll
    for (int j = 0; j < 4; j++) {
        int idx = lane * 4 + j;
        if (idx < nb) bsum[idx] = run;
        run += v[j];
    }
}

__global__ void scan3_kernel(int* __restrict__ rowptr, int* __restrict__ fill,
                             const int* __restrict__ bsum, int n, int E)
{
    int gid = blockIdx.x * blockDim.x + threadIdx.x;
    if (gid < n) {
        int v = rowptr[gid] + bsum[gid >> 10];
        rowptr[gid] = v;
        fill[gid] = v;
    }
    if (gid == 0) rowptr[n] = E;
}

__global__ void permute_kernel(
    const int* __restrict__ src, const int* __restrict__ dst,
    const float* __restrict__ val, int* __restrict__ fill,
    int2* __restrict__ es, int E)
{
    int i = (blockIdx.x * blockDim.x + threadIdx.x) * 2;
    if (i + 1 < E) {
        int2   s = *reinterpret_cast<const int2*>(src + i);
        int2   d = *reinterpret_cast<const int2*>(dst + i);
        float2 v = *reinterpret_cast<const float2*>(val + i);
        int p0 = atomicAdd(&fill[d.x], 1);
        int p1 = atomicAdd(&fill[d.y], 1);
        __stcs(es + p0, make_int2(s.x, __float_as_int(v.x)));
        __stcs(es + p1, make_int2(s.y, __float_as_int(v.y)));
    } else if (i < E) {
        int p = atomicAdd(&fill[dst[i]], 1);
        __stcs(es + p, make_int2(src[i], __float_as_int(val[i])));
    }
}

// ---------------------------------------------------------------------------
// Gather from fp16 h (round-6 version: best measured).
// One warp per dst node, 8-deep pipeline, __ldcs es, __stcs out, fused bias.
// ---------------------------------------------------------------------------
__device__ __forceinline__ void hfma4(float4& acc, uint2 q, float v)
{
    __half2 a = *reinterpret_cast<__half2*>(&q.x);
    __half2 b = *reinterpret_cast<__half2*>(&q.y);
    float2 fa = __half22float2(a);
    float2 fb = __half22float2(b);
    acc.x = fmaf(fa.x, v, acc.x); acc.y = fmaf(fa.y, v, acc.y);
    acc.z = fmaf(fb.x, v, acc.z); acc.w = fmaf(fb.y, v, acc.w);
}

__global__ __launch_bounds__(256) void gather_kernel(
    const __half* __restrict__ h, const int* __restrict__ rowptr,
    const int2* __restrict__ es, const float* __restrict__ bias,
    float* __restrict__ out, int N)
{
    const int lane = threadIdx.x & 31;
    const int warp = (blockIdx.x * blockDim.x + threadIdx.x) >> 5;
    const int nw   = (gridDim.x * blockDim.x) >> 5;

    const float4 bv = *reinterpret_cast<const float4*>(bias + lane * 4);
    const int col4 = lane * 4;

    for (int d = warp; d < N; d += nw) {
        const int beg = rowptr[d];
        const int end = rowptr[d + 1];
        float4 acc = bv;

        int e = beg;
        for (; e + 7 < end; e += 8) {
            int2 ev[8];
#pragma unroll
            for (int j = 0; j < 8; j++) ev[j] = __ldcs(es + e + j);
            uint2 q[8];
#pragma unroll
            for (int j = 0; j < 8; j++)
                q[j] = *reinterpret_cast<const uint2*>(h + (size_t)ev[j].x * OUT_DIM + col4);
#pragma unroll
            for (int j = 0; j < 8; j++) hfma4(acc, q[j], __int_as_float(ev[j].y));
        }
        for (; e < end; e++) {
            const int2 ev = __ldcs(es + e);
            uint2 q = *reinterpret_cast<const uint2*>(h + (size_t)ev.x * OUT_DIM + col4);
            hfma4(acc, q, __int_as_float(ev.y));
        }
        __stcs(reinterpret_cast<float4*>(out + (size_t)d * OUT_DIM + col4), acc);
    }
}

// ---------------------------------------------------------------------------
// Launch: side = CSR build, main = transpose -> gemm (launch idx 3) -> gather.
// ---------------------------------------------------------------------------
extern "C" void kernel_launch(void* const* d_in, const int* in_sizes, int n_in,
                              void* d_out, int out_size)
{
    const float* X    = (const float*)d_in[0];   // [N, 256]
    const int*   src  = (const int*)  d_in[1];   // [E]
    const int*   dst  = (const int*)  d_in[2];   // [E]
    const float* vals = (const float*)d_in[3];   // [E]
    const float* W    = (const float*)d_in[4];   // [256, 128]
    const float* b    = (const float*)d_in[5];   // [128]
    float* out = (float*)d_out;                  // [N, 128]

    const int N = in_sizes[0] / IN_DIM;
    const int E = in_sizes[1];

    __half*   Hh;     cudaGetSymbolAddress((void**)&Hh,      g_hh);
    uint32_t* WT;     cudaGetSymbolAddress((void**)&WT,      g_wt);
    int*      deg;    cudaGetSymbolAddress((void**)&deg,     g_deg);
    int*      rowptr; cudaGetSymbolAddress((void**)&rowptr,  g_rowptr);
    int*      fill;   cudaGetSymbolAddress((void**)&fill,    g_fill);
    int*      bsum;   cudaGetSymbolAddress((void**)&bsum,    g_bsum);
    int2*     es;     cudaGetSymbolAddress((void**)&es,      g_esorted);

    const int nb = (N + 1023) / 1024;

    static cudaStream_t s_side = nullptr;
    static cudaEvent_t  e_fork = nullptr, e_join = nullptr;
    if (s_side == nullptr) {
        cudaStreamCreateWithFlags(&s_side, cudaStreamNonBlocking);
        cudaEventCreateWithFlags(&e_fork, cudaEventDisableTiming);
        cudaEventCreateWithFlags(&e_join, cudaEventDisableTiming);
    }

    // Fork side stream.
    cudaEventRecord(e_fork, 0);
    cudaStreamWaitEvent(s_side, e_fork, 0);

    // Side: zero degrees (memset node), histogram, first scan stage.
    cudaMemsetAsync(deg, 0, (size_t)N * sizeof(int), s_side);
    hist_kernel<<<(E / 4 + 255) / 256, 256, 0, s_side>>>(dst, deg, E);      // k0
    scan1_kernel<<<nb, 1024, 0, s_side>>>(deg, rowptr, bsum, N);            // k1

    // Main: transpose(+tf32 pack), then GEMM (kernel idx 3 -> ncu target).
    transpose_w_kernel<<<(IN_DIM * OUT_DIM + 255) / 256, 256>>>(W, WT);     // k2
    gemm_mma_kernel<<<(N + 127) / 128, 256>>>(X, WT, Hh, N);                // k3

    // Side: rest of the build.
    scan2_kernel<<<1, 32, 0, s_side>>>(bsum, nb);                           // k4
    scan3_kernel<<<(N + 255) / 256, 256, 0, s_side>>>(rowptr, fill, bsum, N, E); // k5
    permute_kernel<<<(E / 2 + 255) / 256, 256, 0, s_side>>>(src, dst, vals, fill, es, E); // k6
    cudaEventRecord(e_join, s_side);

    // Join, then gather with fused bias.
    cudaStreamWaitEvent(0, e_join, 0);
    gather_kernel<<<(N * 32 + 255) / 256, 256>>>(Hh, rowptr, es, b, out, N); // k7
}